// round 10
// baseline (speedup 1.0000x reference)
#include <cuda_runtime.h>
#include <cuda_bf16.h>
#include <cuda_fp16.h>
#include <cstdint>
#include <math.h>

#define S_LEN 2048
#define HID   2048
#define NH    32
#define NKV   4
#define HD    128
#define NQ    (NH * HD)    // 4096
#define NKVD  (NKV * HD)   // 512
#define NQKV  (NQ + 2 * NKVD)  // 5120

// ---------------------------------------------------------------------------
// Scratch (device globals — no allocation allowed)
// ---------------------------------------------------------------------------
__device__ float g_qkv[S_LEN * NQKV];
__device__ float g_attn[S_LEN * NQ];

__device__ int8_t g_x8h[S_LEN * HID];
__device__ int8_t g_x8l[S_LEN * HID];
__device__ int8_t g_w8h[NQKV * HID];
__device__ int8_t g_w8l[NQKV * HID];
__device__ int8_t g_wo8h[HID * NQ];
__device__ int8_t g_wo8l[HID * NQ];
__device__ int8_t g_a8h[S_LEN * NQ];
__device__ int8_t g_a8l[S_LEN * NQ];

__device__ float g_sx[S_LEN];
__device__ float g_sw[NQKV];
__device__ float g_swo[HID];
__device__ float g_sat[S_LEN];

__device__ __half g_q16h[S_LEN * NQ];
__device__ __half g_q16l[S_LEN * NQ];
__device__ __half g_k16h[S_LEN * NKVD];
__device__ __half g_v16[S_LEN * NKVD];

// ---------------------------------------------------------------------------
// helpers
// ---------------------------------------------------------------------------
__device__ __forceinline__ uint32_t smem_u32(const void* p) {
    uint32_t a;
    asm("{ .reg .u64 t; cvta.to.shared.u64 t, %1; cvt.u32.u64 %0, t; }"
        : "=r"(a) : "l"(p));
    return a;
}

__device__ __forceinline__ void cpa16(uint32_t dst, const void* src) {
    asm volatile(
        "{\n\t.reg .u64 g;\n\tcvta.to.global.u64 g, %1;\n\t"
        "cp.async.cg.shared.global [%0], [g], 16;\n\t}"
        :: "r"(dst), "l"(src) : "memory");
}
#define CPA_COMMIT() asm volatile("cp.async.commit_group;" ::: "memory")
#define CPA_WAIT1()  asm volatile("cp.async.wait_group 1;" ::: "memory")
#define CPA_WAIT0()  asm volatile("cp.async.wait_group 0;" ::: "memory")

#define LDSM4(r, addr) \
    asm volatile("ldmatrix.sync.aligned.m8n8.x4.shared.b16 {%0,%1,%2,%3}, [%4];" \
        : "=r"((r)[0]), "=r"((r)[1]), "=r"((r)[2]), "=r"((r)[3]) : "r"(addr))

// s8 MMA: m16n8k32, s32 accumulator (4096 MACs/instr)
__device__ __forceinline__ void mma_s8(int32_t* d, const uint32_t* a,
                                       uint32_t b0, uint32_t b1) {
    asm volatile(
        "mma.sync.aligned.m16n8k32.row.col.s32.s8.s8.s32 "
        "{%0,%1,%2,%3}, {%4,%5,%6,%7}, {%8,%9}, {%0,%1,%2,%3};"
        : "+r"(d[0]), "+r"(d[1]), "+r"(d[2]), "+r"(d[3])
        : "r"(a[0]), "r"(a[1]), "r"(a[2]), "r"(a[3]), "r"(b0), "r"(b1));
}

// Fast exp on the FFMA pipe. Rel err < 3e-6 on [-87, 0].
__device__ __forceinline__ float fexp(float x) {
    x = fmaxf(x, -87.0f);
    float z  = fmaf(x, 1.44269504089f, 12582912.0f);
    float nf = z - 12582912.0f;
    float f  = fmaf(x, 1.44269504089f, -nf);
    float p  = 1.333355815e-3f;
    p = fmaf(p, f, 9.618129107e-3f);
    p = fmaf(p, f, 5.550410866e-2f);
    p = fmaf(p, f, 2.402265069e-1f);
    p = fmaf(p, f, 6.931471806e-1f);
    p = fmaf(p, f, 1.0f);
    int n = __float_as_int(z) - 0x4B400000;
    return __int_as_float(__float_as_int(p) + (n << 23));
}

// ---------------------------------------------------------------------------
// Quantization kernels
// ---------------------------------------------------------------------------
// Per-row 2-level int8 quantization: x ~= s * (H + L/128)
__global__ __launch_bounds__(256) void quant_rows(
    const float* __restrict__ in, int8_t* __restrict__ oh,
    int8_t* __restrict__ ol, float* __restrict__ scl, int cols)
{
    const int row = blockIdx.x;
    const int tid = threadIdx.x;
    const float* p = in + (size_t)row * cols;

    float m = 0.0f;
    for (int i = tid; i < cols; i += 256) m = fmaxf(m, fabsf(p[i]));
#pragma unroll
    for (int off = 16; off > 0; off >>= 1)
        m = fmaxf(m, __shfl_xor_sync(0xffffffffu, m, off));
    __shared__ float red[8];
    if ((tid & 31) == 0) red[tid >> 5] = m;
    __syncthreads();
    float mx = fmaxf(fmaxf(fmaxf(red[0], red[1]), fmaxf(red[2], red[3])),
                     fmaxf(fmaxf(red[4], red[5]), fmaxf(red[6], red[7])));
    mx = fmaxf(mx, 1e-20f);
    if (tid == 0) scl[row] = mx * (1.0f / 127.0f);
    const float inv = 127.0f / mx;

    int8_t* ph = oh + (size_t)row * cols;
    int8_t* pl = ol + (size_t)row * cols;
    for (int i = tid; i < cols; i += 256) {
        float a  = p[i] * inv;
        float ah = rintf(a);
        float al = rintf(128.0f * (a - ah));
        ph[i] = (int8_t)(int)ah;
        pl[i] = (int8_t)(int)al;
    }
}

// Column-max of W[R][C] -> per-column scale
__global__ void colmax(const float* __restrict__ w, float* __restrict__ scl,
                       int R, int C)
{
    int c = blockIdx.x * blockDim.x + threadIdx.x;
    if (c >= C) return;
    float m = 0.0f;
    for (int r = 0; r < R; r++) m = fmaxf(m, fabsf(w[(size_t)r * C + c]));
    scl[c] = fmaxf(m, 1e-20f) * (1.0f / 127.0f);
}

// Transpose [R][C] fp32 -> [C][R] int8 hi/lo with per-output-row scale
__global__ void transpose_quant(const float* __restrict__ in,
                                int8_t* __restrict__ oh, int8_t* __restrict__ ol,
                                const float* __restrict__ scl, int R, int C)
{
    __shared__ float t[32][33];
    int c0 = blockIdx.x << 5, r0 = blockIdx.y << 5;
    int x = threadIdx.x, y = threadIdx.y;
#pragma unroll
    for (int j = y; j < 32; j += 8)
        t[j][x] = in[(size_t)(r0 + j) * C + c0 + x];
    __syncthreads();
#pragma unroll
    for (int j = y; j < 32; j += 8) {
        int col = c0 + j;
        float a  = t[x][j] / scl[col];
        float ah = rintf(a);
        float al = rintf(128.0f * (a - ah));
        size_t o = (size_t)col * R + r0 + x;
        oh[o] = (int8_t)(int)ah;
        ol[o] = (int8_t)(int)al;
    }
}

__global__ void cvt_v16(const float* __restrict__ qkv, __half* __restrict__ out)
{
    int i = blockIdx.x * blockDim.x + threadIdx.x;
    int s = i >> 9, d = i & 511;
    out[i] = __float2half(qkv[(size_t)s * NQKV + NQ + NKVD + d]);
}

// ---------------------------------------------------------------------------
// INT8 3-term MMA GEMM: C[m][n] = sa[m]*sb[n]*(AhBh + (AhBl+AlBh)/128)
// CTA 128x128, 8 warps, warp tile 64x32. K chunks of 64 int8, 2-stage cp.async.
// Smem rows: 64 B data + 16 pad (same conflict-free pattern as fp16 version;
// s8 k32 fragments are byte-identical to f16 k16 under ldmatrix).
// ---------------------------------------------------------------------------
#define RPAD_B 80
#define TILE_B (128 * RPAD_B)            // 10240
#define STG_B  (4 * TILE_B)              // 40960: Ah, Al, Bh, Bl
#define GEMM_SMEM (2 * STG_B)            // 81920

__global__ void __launch_bounds__(256) gemm_mma_s8(
    const int8_t* __restrict__ Ah, const int8_t* __restrict__ Al,
    const int8_t* __restrict__ Bh, const int8_t* __restrict__ Bl,
    const float* __restrict__ sa, const float* __restrict__ sb,
    float* __restrict__ C, int N, int K)
{
    extern __shared__ char smraw[];
    const int tid  = threadIdx.x;
    const int wid  = tid >> 5, lane = tid & 31;
    const int m0 = blockIdx.y << 7, n0 = blockIdx.x << 7;
    const int wm = wid >> 2;             // 0..1  (64-row slab)
    const int wn = wid & 3;              // 0..3  (32-col slab)

    const uint32_t sbase = smem_u32(smraw);

    int32_t acc0[4][4][4];               // AhBh
    int32_t acc1[4][4][4];               // AhBl + AlBh
#pragma unroll
    for (int i = 0; i < 4; i++)
#pragma unroll
        for (int j = 0; j < 4; j++)
#pragma unroll
            for (int r = 0; r < 4; r++) { acc0[i][j][r] = 0; acc1[i][j][r] = 0; }

    const uint32_t lrow = lane & 15;
    const uint32_t lkof = (lane >> 4) << 4;

    const int8_t* gb[4] = {Ah, Al, Bh, Bl};
    const int gr0[4] = {m0, m0, n0, n0};
    const int nck = K >> 6;              // 64 int8 per chunk

    auto load_stage = [&](int ck, int s) {
        const int k0 = ck << 6;
        const uint32_t sb_ = sbase + s * STG_B;
#pragma unroll
        for (int t = 0; t < 4; t++) {
#pragma unroll
            for (int i = 0; i < 2; i++) {
                int idx = (i << 8) + tid;          // 0..511
                int row = idx >> 2, c = idx & 3;
                cpa16(sb_ + t * TILE_B + row * RPAD_B + c * 16,
                      gb[t] + (size_t)(gr0[t] + row) * K + k0 + c * 16);
            }
        }
        CPA_COMMIT();
    };

    load_stage(0, 0);

    for (int ck = 0; ck < nck; ck++) {
        if (ck + 1 < nck) { load_stage(ck + 1, (ck + 1) & 1); CPA_WAIT1(); }
        else             { CPA_WAIT0(); }
        __syncthreads();

        const uint32_t sb_ = sbase + (ck & 1) * STG_B;
        const uint32_t aHb = sb_ + (wm * 64 + lrow) * RPAD_B + lkof;
        const uint32_t aLb = aHb + TILE_B;
        const uint32_t bHb = sb_ + 2 * TILE_B + (wn * 32 + lrow) * RPAD_B + lkof;
        const uint32_t bLb = bHb + TILE_B;

#pragma unroll
        for (int kk = 0; kk < 2; kk++) {           // two k32 slabs (32 B each)
            const uint32_t ko = kk * 32;
            uint32_t bh[2][4], bl[2][4];
#pragma unroll
            for (int np = 0; np < 2; np++) {
                LDSM4(bh[np], bHb + np * 16 * RPAD_B + ko);
                LDSM4(bl[np], bLb + np * 16 * RPAD_B + ko);
            }
#pragma unroll
            for (int mt = 0; mt < 4; mt++) {
                uint32_t ah[4], al[4];
                LDSM4(ah, aHb + mt * 16 * RPAD_B + ko);
                LDSM4(al, aLb + mt * 16 * RPAD_B + ko);
#pragma unroll
                for (int nt = 0; nt < 4; nt++) {
                    const int np = nt >> 1, sl = nt & 1;
                    mma_s8(acc0[mt][nt], ah, bh[np][sl], bh[np][sl + 2]);
                    mma_s8(acc1[mt][nt], ah, bl[np][sl], bl[np][sl + 2]);
                    mma_s8(acc1[mt][nt], al, bh[np][sl], bh[np][sl + 2]);
                }
            }
        }
        __syncthreads();
    }

    // Epilogue: dequantize and store fp32
    const int erow = (lane >> 2);
    const int ecol = (lane & 3) << 1;
#pragma unroll
    for (int mt = 0; mt < 4; mt++) {
        const int r  = m0 + wm * 64 + mt * 16 + erow;
        const float sa0 = sa[r], sa1 = sa[r + 8];
#pragma unroll
        for (int nt = 0; nt < 4; nt++) {
            const int c = n0 + wn * 32 + nt * 8 + ecol;
            const float sb0 = sb[c], sb1 = sb[c + 1];
            float v0 = ((float)acc0[mt][nt][0] + (float)acc1[mt][nt][0] * 0.0078125f) * sa0 * sb0;
            float v1 = ((float)acc0[mt][nt][1] + (float)acc1[mt][nt][1] * 0.0078125f) * sa0 * sb1;
            float v2 = ((float)acc0[mt][nt][2] + (float)acc1[mt][nt][2] * 0.0078125f) * sa1 * sb0;
            float v3 = ((float)acc0[mt][nt][3] + (float)acc1[mt][nt][3] * 0.0078125f) * sa1 * sb1;
            *(float2*)(C + (size_t)r * N + c)       = make_float2(v0, v1);
            *(float2*)(C + (size_t)(r + 8) * N + c) = make_float2(v2, v3);
        }
    }
}

// ---------------------------------------------------------------------------
// Fused RMSNorm + RoPE, reading a column slice of fused qkv -> fp16 hi/lo
// ---------------------------------------------------------------------------
__global__ __launch_bounds__(128) void rmsnorm_rope_f16(
    const float* __restrict__ qkv, int colOff, const float* __restrict__ w,
    const float* __restrict__ cs, const float* __restrict__ sn, int heads,
    __half* __restrict__ oh, __half* __restrict__ ol)
{
    const int b = blockIdx.x;
    const int s = b / heads;
    const int h = b - s * heads;
    const int d = threadIdx.x;

    const size_t io = (size_t)s * NQKV + colOff + h * HD;
    const size_t oo = ((size_t)s * heads + h) * HD;
    float v = qkv[io + d];

    float ssq = v * v;
#pragma unroll
    for (int off = 16; off > 0; off >>= 1)
        ssq += __shfl_xor_sync(0xffffffffu, ssq, off);

    __shared__ float red[4];
    __shared__ float sh[HD];
    if ((d & 31) == 0) red[d >> 5] = ssq;
    __syncthreads();
    float tot = red[0] + red[1] + red[2] + red[3];

    float xn = v * rsqrtf(tot * (1.0f / HD) + 1e-6f) * w[d];
    sh[d] = xn;
    __syncthreads();

    float partner = (d < 64) ? -sh[d + 64] : sh[d - 64];
    float res = xn * cs[s * HD + d] + partner * sn[s * HD + d];

    __half h16 = __float2half(res);
    oh[oo + d] = h16;
    if (ol) ol[oo + d] = __float2half(res - __half2float(h16));
}

// ---------------------------------------------------------------------------
// Tensor-core flash attention, double-buffered K/V prefetch (proven R8 path).
// Output: fp32 attn (quantized afterwards for the int8 out-projection).
// ---------------------------------------------------------------------------
#include <mma.h>
using namespace nvcuda;

#define QLD 136
#define SLD 132
#define PLD 72

#define OFF_QH 0
#define OFF_QL 17408
#define OFF_KV 34816          // per-buf: KH +0, V +17408
#define KVBUF  34816
#define OFF_S  104448
#define OFF_P  138240
#define OFF_O  147456
#define OFF_M  180224
#define OFF_L  180480
#define OFF_AL 180736
#define FLASH_SMEM 180992

__global__ void __launch_bounds__(256) flash_wmma(
    const __half* __restrict__ qh, const __half* __restrict__ ql,
    const __half* __restrict__ kh, const __half* __restrict__ vv,
    float* __restrict__ attn)
{
    extern __shared__ char smc[];
    __half* sQh = (__half*)(smc + OFF_QH);
    __half* sQl = (__half*)(smc + OFF_QL);
    float*  sS  = (float*)(smc + OFF_S);
    __half* sP  = (__half*)(smc + OFF_P);
    float*  sO  = (float*)(smc + OFF_O);
    float*  sM  = (float*)(smc + OFF_M);
    float*  sL  = (float*)(smc + OFF_L);
    float*  sA  = (float*)(smc + OFF_AL);

    const int h     = blockIdx.x;
    const int ptile = (int)gridDim.y - 1 - blockIdx.y;
    const int m0    = ptile << 6;
    const int kvh   = h >> 3;
    const int tid   = threadIdx.x;
    const int wid   = tid >> 5;
    const int rs    = wid >> 1;
    const int ch    = wid & 1;
    const float scale = 0.08838834764831845f;

    auto load_kv = [&](int kb, int buf) {
        const int k0g = kb << 6;
        const uint32_t base = smem_u32(smc) + OFF_KV + buf * KVBUF;
#pragma unroll
        for (int i = 0; i < 4; i++) {
            int idx = tid + (i << 8);
            int r = idx >> 4, c = idx & 15;
            size_t so = (size_t)(k0g + r) * NKVD + kvh * HD + (c << 3);
            uint32_t off = r * (QLD * 2) + (c << 4);
            cpa16(base + off,         kh + so);
            cpa16(base + 17408 + off, vv + so);
        }
        CPA_COMMIT();
    };

    {
        uint32_t dqh = smem_u32(sQh), dql = smem_u32(sQl);
#pragma unroll
        for (int i = 0; i < 4; i++) {
            int idx = tid + (i << 8);
            int r = idx >> 4, c = idx & 15;
            size_t so = (size_t)(m0 + r) * NQ + h * HD + (c << 3);
            uint32_t off = r * (QLD * 2) + (c << 4);
            cpa16(dqh + off, qh + so);
            cpa16(dql + off, ql + so);
        }
        CPA_COMMIT();
    }
    load_kv(0, 0);

    for (int i = tid; i < 64 * 128 / 4; i += 256)
        ((float4*)sO)[i] = make_float4(0.f, 0.f, 0.f, 0.f);
    if (tid < 64) { sM[tid] = -1e30f; sL[tid] = 0.f; }

    for (int kb = 0; kb <= ptile; kb++) {
        const int k0g = kb << 6;
        const int buf = kb & 1;
        __half* sKh = (__half*)(smc + OFF_KV + buf * KVBUF);
        __half* sV  = (__half*)(smc + OFF_KV + buf * KVBUF + 17408);

        if (kb < ptile) { load_kv(kb + 1, buf ^ 1); CPA_WAIT1(); }
        else            { CPA_WAIT0(); }
        __syncthreads();

        // --- QK^T: (Qh + Ql) x Kh ---
        {
            wmma::fragment<wmma::accumulator, 16, 16, 16, float> accS[2];
            wmma::fill_fragment(accS[0], 0.0f);
            wmma::fill_fragment(accS[1], 0.0f);
#pragma unroll
            for (int k0 = 0; k0 < 128; k0 += 16) {
                wmma::fragment<wmma::matrix_a, 16, 16, 16, __half, wmma::row_major> ah, al;
                wmma::load_matrix_sync(ah, sQh + rs * 16 * QLD + k0, QLD);
                wmma::load_matrix_sync(al, sQl + rs * 16 * QLD + k0, QLD);
#pragma unroll
                for (int j = 0; j < 2; j++) {
                    wmma::fragment<wmma::matrix_b, 16, 16, 16, __half, wmma::col_major> bh;
                    int kcol = ch * 32 + j * 16;
                    wmma::load_matrix_sync(bh, sKh + kcol * QLD + k0, QLD);
                    wmma::mma_sync(accS[j], ah, bh, accS[j]);
                    wmma::mma_sync(accS[j], al, bh, accS[j]);
                }
            }
#pragma unroll
            for (int j = 0; j < 2; j++)
                wmma::store_matrix_sync(sS + rs * 16 * SLD + ch * 32 + j * 16,
                                        accS[j], SLD, wmma::mem_row_major);
        }
        __syncthreads();

        // --- online softmax ---
        {
            const int r  = tid >> 2;
            const int q4 = tid & 3;
            float* srow = sS + r * SLD + q4 * 16;
            const int qglob = m0 + r;
            const int kbase = k0g + q4 * 16;

            float vals[16];
            float mx = -1e30f;
#pragma unroll
            for (int j = 0; j < 16; j++) {
                float s = srow[j];
                s = (kbase + j <= qglob) ? s * scale : -1e30f;
                vals[j] = s;
                mx = fmaxf(mx, s);
            }
            mx = fmaxf(mx, __shfl_xor_sync(0xffffffffu, mx, 1));
            mx = fmaxf(mx, __shfl_xor_sync(0xffffffffu, mx, 2));

            float mold = sM[r];
            float mnew = fmaxf(mold, mx);
            float alpha = fexp(mold - mnew);

            __half* prow = sP + r * PLD + q4 * 16;
            float lsum = 0.f;
#pragma unroll
            for (int j = 0; j < 16; j++) {
                float p = fexp(vals[j] - mnew);
                prow[j] = __float2half(p);
                lsum += p;
            }
            lsum += __shfl_xor_sync(0xffffffffu, lsum, 1);
            lsum += __shfl_xor_sync(0xffffffffu, lsum, 2);

            if (q4 == 0) {
                sM[r] = mnew;
                sL[r] = sL[r] * alpha + lsum;
                sA[r] = alpha;
            }
        }
        __syncthreads();

        // --- P @ V ---
        {
            wmma::fragment<wmma::accumulator, 16, 16, 16, float> accO[4];
#pragma unroll
            for (int j = 0; j < 4; j++) wmma::fill_fragment(accO[j], 0.0f);
#pragma unroll
            for (int k0 = 0; k0 < 64; k0 += 16) {
                wmma::fragment<wmma::matrix_a, 16, 16, 16, __half, wmma::row_major> a;
                wmma::load_matrix_sync(a, sP + rs * 16 * PLD + k0, PLD);
#pragma unroll
                for (int j = 0; j < 4; j++) {
                    wmma::fragment<wmma::matrix_b, 16, 16, 16, __half, wmma::row_major> b;
                    wmma::load_matrix_sync(b, sV + k0 * QLD + ch * 64 + j * 16, QLD);
                    wmma::mma_sync(accO[j], a, b, accO[j]);
                }
            }
#pragma unroll
            for (int j = 0; j < 4; j++)
                wmma::store_matrix_sync(sS + rs * 16 * SLD + ch * 64 + j * 16,
                                        accO[j], SLD, wmma::mem_row_major);
        }
        __syncthreads();

        // --- O = O*alpha + PV ---
        {
            const int r  = tid >> 2;
            const int c0 = (tid & 3) << 5;
            const float a = sA[r];
            float4* op = (float4*)(sO + r * 128 + c0);
            const float4* pv = (const float4*)(sS + r * SLD + c0);
#pragma unroll
            for (int j = 0; j < 8; j++) {
                float4 o = op[j], p = pv[j];
                o.x = o.x * a + p.x;
                o.y = o.y * a + p.y;
                o.z = o.z * a + p.z;
                o.w = o.w * a + p.w;
                op[j] = o;
            }
        }
        __syncthreads();
    }

    // Epilogue: normalize, write fp32 attn
    {
        const int r  = tid >> 2;
        const int c0 = (tid & 3) << 5;
        const float inv = 1.0f / sL[r];
        float* base = attn + (size_t)(m0 + r) * NQ + h * HD + c0;
#pragma unroll
        for (int j = 0; j < 32; j += 4) {
            float4 o;
            o.x = sO[r * 128 + c0 + j]     * inv;
            o.y = sO[r * 128 + c0 + j + 1] * inv;
            o.z = sO[r * 128 + c0 + j + 2] * inv;
            o.w = sO[r * 128 + c0 + j + 3] * inv;
            *(float4*)(base + j) = o;
        }
    }
}

// ---------------------------------------------------------------------------
extern "C" void kernel_launch(void* const* d_in, const int* in_sizes, int n_in,
                              void* d_out, int out_size)
{
    (void)in_sizes; (void)n_in; (void)out_size;
    const float* x  = (const float*)d_in[0];
    const float* wq = (const float*)d_in[1];
    const float* wk = (const float*)d_in[2];
    const float* wv = (const float*)d_in[3];
    const float* wo = (const float*)d_in[4];
    const float* qn = (const float*)d_in[5];
    const float* kn = (const float*)d_in[6];
    const float* cs = (const float*)d_in[7];
    const float* sn = (const float*)d_in[8];
    float* out = (float*)d_out;

    float *qkv, *attn, *sx, *sw, *swo, *sat;
    cudaGetSymbolAddress((void**)&qkv,  g_qkv);
    cudaGetSymbolAddress((void**)&attn, g_attn);
    cudaGetSymbolAddress((void**)&sx,   g_sx);
    cudaGetSymbolAddress((void**)&sw,   g_sw);
    cudaGetSymbolAddress((void**)&swo,  g_swo);
    cudaGetSymbolAddress((void**)&sat,  g_sat);

    int8_t *x8h, *x8l, *w8h, *w8l, *wo8h, *wo8l, *a8h, *a8l;
    cudaGetSymbolAddress((void**)&x8h,  g_x8h);
    cudaGetSymbolAddress((void**)&x8l,  g_x8l);
    cudaGetSymbolAddress((void**)&w8h,  g_w8h);
    cudaGetSymbolAddress((void**)&w8l,  g_w8l);
    cudaGetSymbolAddress((void**)&wo8h, g_wo8h);
    cudaGetSymbolAddress((void**)&wo8l, g_wo8l);
    cudaGetSymbolAddress((void**)&a8h,  g_a8h);
    cudaGetSymbolAddress((void**)&a8l,  g_a8l);

    __half *q16h, *q16l, *k16h, *v16;
    cudaGetSymbolAddress((void**)&q16h, g_q16h);
    cudaGetSymbolAddress((void**)&q16l, g_q16l);
    cudaGetSymbolAddress((void**)&k16h, g_k16h);
    cudaGetSymbolAddress((void**)&v16,  g_v16);

    cudaFuncSetAttribute(gemm_mma_s8,
                         cudaFuncAttributeMaxDynamicSharedMemorySize, GEMM_SMEM);
    cudaFuncSetAttribute(flash_wmma,
                         cudaFuncAttributeMaxDynamicSharedMemorySize, FLASH_SMEM);

    // Quantize activations per-row (2-level int8)
    quant_rows<<<S_LEN, 256>>>(x, x8h, x8l, sx, HID);

    // Per-output-column weight scales, then transpose+quantize to [N][K] int8
    colmax<<<(NQ + 255) / 256, 256>>>(wq, sw, HID, NQ);
    colmax<<<(NKVD + 255) / 256, 256>>>(wk, sw + NQ, HID, NKVD);
    colmax<<<(NKVD + 255) / 256, 256>>>(wv, sw + NQ + NKVD, HID, NKVD);
    colmax<<<(HID + 255) / 256, 256>>>(wo, swo, NQ, HID);

    transpose_quant<<<dim3(NQ / 32,   HID / 32), dim3(32, 8)>>>(
        wq, w8h, w8l, sw, HID, NQ);
    transpose_quant<<<dim3(NKVD / 32, HID / 32), dim3(32, 8)>>>(
        wk, w8h + (size_t)NQ * HID, w8l + (size_t)NQ * HID, sw + NQ, HID, NKVD);
    transpose_quant<<<dim3(NKVD / 32, HID / 32), dim3(32, 8)>>>(
        wv, w8h + (size_t)(NQ + NKVD) * HID, w8l + (size_t)(NQ + NKVD) * HID,
        sw + NQ + NKVD, HID, NKVD);
    transpose_quant<<<dim3(HID / 32,  NQ / 32),  dim3(32, 8)>>>(
        wo, wo8h, wo8l, swo, NQ, HID);

    // Fused QKV projection (int8 3-term MMA): grid (5120/128, 2048/128)
    gemm_mma_s8<<<dim3(NQKV / 128, S_LEN / 128), 256, GEMM_SMEM>>>(
        x8h, x8l, w8h, w8l, sx, sw, qkv, NQKV, HID);

    // RMSNorm + RoPE -> fp16 hi/lo (K: hi only); V -> fp16
    rmsnorm_rope_f16<<<S_LEN * NH,  128>>>(qkv, 0,  qn, cs, sn, NH,  q16h, q16l);
    rmsnorm_rope_f16<<<S_LEN * NKV, 128>>>(qkv, NQ, kn, cs, sn, NKV, k16h, (half*)0);
    cvt_v16<<<(S_LEN * NKVD) / 256, 256>>>(qkv, v16);

    // Flash attention -> fp32 attn
    flash_wmma<<<dim3(NH, S_LEN / 64), 256, FLASH_SMEM>>>(
        q16h, q16l, k16h, v16, attn);

    // Quantize attn rows, then int8 output projection
    quant_rows<<<S_LEN, 256>>>(attn, a8h, a8l, sat, NQ);
    gemm_mma_s8<<<dim3(HID / 128, S_LEN / 128), 256, GEMM_SMEM>>>(
        a8h, a8l, wo8h, wo8l, sat, swo, out, HID, NQ);
}

// round 11
// speedup vs baseline: 3.1908x; 3.1908x over previous
#include <cuda_runtime.h>
#include <cuda_bf16.h>
#include <cuda_fp16.h>
#include <cstdint>
#include <math.h>

#define S_LEN 2048
#define HID   2048
#define NH    32
#define NKV   4
#define HD    128
#define NQ    (NH * HD)    // 4096
#define NKVD  (NKV * HD)   // 512
#define NQKV  (NQ + 2 * NKVD)  // 5120

// ---------------------------------------------------------------------------
// Scratch (device globals — no allocation allowed)
// ---------------------------------------------------------------------------
__device__ float g_qkv[S_LEN * NQKV];

__device__ __half g_x16[S_LEN * HID];
__device__ __half g_wqkvT[NQKV * HID];   // fp16 weights, [N][K]
__device__ __half g_woT[HID * NQ];
__device__ __half g_at16[S_LEN * NQ];

__device__ __half g_q16h[S_LEN * NQ];
__device__ __half g_q16l[S_LEN * NQ];
__device__ __half g_k16h[S_LEN * NKVD];
__device__ __half g_v16[S_LEN * NKVD];

// ---------------------------------------------------------------------------
// helpers
// ---------------------------------------------------------------------------
__device__ __forceinline__ uint32_t smem_u32(const void* p) {
    uint32_t a;
    asm("{ .reg .u64 t; cvta.to.shared.u64 t, %1; cvt.u32.u64 %0, t; }"
        : "=r"(a) : "l"(p));
    return a;
}

__device__ __forceinline__ void cpa16(uint32_t dst, const void* src) {
    asm volatile(
        "{\n\t.reg .u64 g;\n\tcvta.to.global.u64 g, %1;\n\t"
        "cp.async.cg.shared.global [%0], [g], 16;\n\t}"
        :: "r"(dst), "l"(src) : "memory");
}
#define CPA_COMMIT() asm volatile("cp.async.commit_group;" ::: "memory")
#define CPA_WAIT1()  asm volatile("cp.async.wait_group 1;" ::: "memory")
#define CPA_WAIT0()  asm volatile("cp.async.wait_group 0;" ::: "memory")

#define LDSM4(r, addr) \
    asm volatile("ldmatrix.sync.aligned.m8n8.x4.shared.b16 {%0,%1,%2,%3}, [%4];" \
        : "=r"((r)[0]), "=r"((r)[1]), "=r"((r)[2]), "=r"((r)[3]) : "r"(addr))

__device__ __forceinline__ void mma16816f(float* d, const uint32_t* a,
                                          uint32_t b0, uint32_t b1) {
    asm volatile(
        "mma.sync.aligned.m16n8k16.row.col.f32.f16.f16.f32 "
        "{%0,%1,%2,%3}, {%4,%5,%6,%7}, {%8,%9}, {%0,%1,%2,%3};"
        : "+f"(d[0]), "+f"(d[1]), "+f"(d[2]), "+f"(d[3])
        : "r"(a[0]), "r"(a[1]), "r"(a[2]), "r"(a[3]), "r"(b0), "r"(b1));
}

// Fast exp on the FFMA pipe. Rel err < 3e-6 on [-87, 0].
__device__ __forceinline__ float fexp(float x) {
    x = fmaxf(x, -87.0f);
    float z  = fmaf(x, 1.44269504089f, 12582912.0f);
    float nf = z - 12582912.0f;
    float f  = fmaf(x, 1.44269504089f, -nf);
    float p  = 1.333355815e-3f;
    p = fmaf(p, f, 9.618129107e-3f);
    p = fmaf(p, f, 5.550410866e-2f);
    p = fmaf(p, f, 2.402265069e-1f);
    p = fmaf(p, f, 6.931471806e-1f);
    p = fmaf(p, f, 1.0f);
    int n = __float_as_int(z) - 0x4B400000;
    return __int_as_float(__float_as_int(p) + (n << 23));
}

// ---------------------------------------------------------------------------
// aux kernels
// ---------------------------------------------------------------------------
__global__ void cvt_f16v(const float4* __restrict__ in,
                         uint2* __restrict__ o, int n4)
{
    int i = blockIdx.x * blockDim.x + threadIdx.x;
    if (i < n4) {
        float4 v = in[i];
        __half2 a = __halves2half2(__float2half(v.x), __float2half(v.y));
        __half2 b = __halves2half2(__float2half(v.z), __float2half(v.w));
        uint2 r;
        r.x = *(uint32_t*)&a; r.y = *(uint32_t*)&b;
        o[i] = r;
    }
}

__global__ void cvt_v16(const float* __restrict__ qkv, __half* __restrict__ out)
{
    int i = blockIdx.x * blockDim.x + threadIdx.x;
    int s = i >> 9, d = i & 511;
    out[i] = __float2half(qkv[(size_t)s * NQKV + NQ + NKVD + d]);
}

// Transpose [R][C] fp32 -> [C][R] fp16
__global__ void transpose_f16(const float* __restrict__ in,
                              __half* __restrict__ o, int R, int C)
{
    __shared__ float t[32][33];
    int c0 = blockIdx.x << 5, r0 = blockIdx.y << 5;
    int x = threadIdx.x, y = threadIdx.y;
#pragma unroll
    for (int j = y; j < 32; j += 8)
        t[j][x] = in[(size_t)(r0 + j) * C + c0 + x];
    __syncthreads();
#pragma unroll
    for (int j = y; j < 32; j += 8)
        o[(size_t)(c0 + j) * R + r0 + x] = __float2half(t[x][j]);
}

// ---------------------------------------------------------------------------
// Raw-HMMA fp16 GEMM: C[m][n] = sum_k A[m][k] * B[n][k]
// CTA 128x128, 8 warps, warp tile 64x32. K chunks of 32, 3-stage cp.async,
// one __syncthreads per chunk. Smem rows 80 B -> conflict-free ldmatrix.
// ---------------------------------------------------------------------------
#define RPAD_B 80
#define TILE_B (128 * RPAD_B)            // 10240
#define STG_B  (2 * TILE_B)              // 20480: A, B
#define GEMM_SMEM (3 * STG_B)            // 61440 (3 stages, 2 CTAs/SM)

__global__ void __launch_bounds__(256, 2) gemm_mma_f16(
    const __half* __restrict__ A, const __half* __restrict__ B,
    float* __restrict__ C, int N, int K)
{
    extern __shared__ char smraw[];
    const int tid  = threadIdx.x;
    const int wid  = tid >> 5, lane = tid & 31;
    const int m0 = blockIdx.y << 7, n0 = blockIdx.x << 7;
    const int wm = wid >> 2;             // 0..1  (64-row slab)
    const int wn = wid & 3;              // 0..3  (32-col slab)

    const uint32_t sbase = smem_u32(smraw);

    float acc[4][4][4];
#pragma unroll
    for (int i = 0; i < 4; i++)
#pragma unroll
        for (int j = 0; j < 4; j++)
#pragma unroll
            for (int r = 0; r < 4; r++) acc[i][j][r] = 0.0f;

    const uint32_t lrow = lane & 15;
    const uint32_t lkof = (lane >> 4) << 4;

    const __half* gb[2] = {A, B};
    const int gr0[2] = {m0, n0};
    const int nck = K >> 5;

    auto load_stage = [&](int ck, int s) {
        const int k0 = ck << 5;
        const uint32_t sb = sbase + s * STG_B;
#pragma unroll
        for (int t = 0; t < 2; t++) {
#pragma unroll
            for (int i = 0; i < 2; i++) {
                int idx = (i << 8) + tid;          // 0..511
                int row = idx >> 2, c = idx & 3;
                cpa16(sb + t * TILE_B + row * RPAD_B + c * 16,
                      gb[t] + (size_t)(gr0[t] + row) * K + k0 + c * 8);
            }
        }
        CPA_COMMIT();
    };

    load_stage(0, 0);
    load_stage(1, 1);

    int s = 0;
    for (int ck = 0; ck < nck; ck++) {
        if (ck + 1 < nck) { CPA_WAIT1(); } else { CPA_WAIT0(); }
        __syncthreads();
        if (ck + 2 < nck) {
            int s2 = s + 2; if (s2 >= 3) s2 -= 3;
            load_stage(ck + 2, s2);
        }

        const uint32_t sb = sbase + s * STG_B;
        const uint32_t ab = sb + (wm * 64 + lrow) * RPAD_B + lkof;
        const uint32_t bb = sb + TILE_B + (wn * 32 + lrow) * RPAD_B + lkof;

#pragma unroll
        for (int kk = 0; kk < 2; kk++) {
            const uint32_t ko = kk * 32;
            uint32_t bh[2][4];
#pragma unroll
            for (int np = 0; np < 2; np++)
                LDSM4(bh[np], bb + np * 16 * RPAD_B + ko);
#pragma unroll
            for (int mt = 0; mt < 4; mt++) {
                uint32_t ah[4];
                LDSM4(ah, ab + mt * 16 * RPAD_B + ko);
#pragma unroll
                for (int nt = 0; nt < 4; nt++) {
                    const int np = nt >> 1, sl = nt & 1;
                    mma16816f(acc[mt][nt], ah, bh[np][sl], bh[np][sl + 2]);
                }
            }
        }
        if (++s >= 3) s -= 3;
    }

    const int erow = (lane >> 2);
    const int ecol = (lane & 3) << 1;
#pragma unroll
    for (int mt = 0; mt < 4; mt++) {
#pragma unroll
        for (int nt = 0; nt < 4; nt++) {
            const int r = m0 + wm * 64 + mt * 16 + erow;
            const int c = n0 + wn * 32 + nt * 8 + ecol;
            *(float2*)(C + (size_t)r * N + c) =
                make_float2(acc[mt][nt][0], acc[mt][nt][1]);
            *(float2*)(C + (size_t)(r + 8) * N + c) =
                make_float2(acc[mt][nt][2], acc[mt][nt][3]);
        }
    }
}

// ---------------------------------------------------------------------------
// Fused RMSNorm + RoPE, reading a column slice of fused qkv -> fp16 hi/lo
// ---------------------------------------------------------------------------
__global__ __launch_bounds__(128) void rmsnorm_rope_f16(
    const float* __restrict__ qkv, int colOff, const float* __restrict__ w,
    const float* __restrict__ cs, const float* __restrict__ sn, int heads,
    __half* __restrict__ oh, __half* __restrict__ ol)
{
    const int b = blockIdx.x;
    const int s = b / heads;
    const int h = b - s * heads;
    const int d = threadIdx.x;

    const size_t io = (size_t)s * NQKV + colOff + h * HD;
    const size_t oo = ((size_t)s * heads + h) * HD;
    float v = qkv[io + d];

    float ssq = v * v;
#pragma unroll
    for (int off = 16; off > 0; off >>= 1)
        ssq += __shfl_xor_sync(0xffffffffu, ssq, off);

    __shared__ float red[4];
    __shared__ float sh[HD];
    if ((d & 31) == 0) red[d >> 5] = ssq;
    __syncthreads();
    float tot = red[0] + red[1] + red[2] + red[3];

    float xn = v * rsqrtf(tot * (1.0f / HD) + 1e-6f) * w[d];
    sh[d] = xn;
    __syncthreads();

    float partner = (d < 64) ? -sh[d + 64] : sh[d - 64];
    float res = xn * cs[s * HD + d] + partner * sn[s * HD + d];

    __half h16 = __float2half(res);
    oh[oo + d] = h16;
    if (ol) ol[oo + d] = __float2half(res - __half2float(h16));
}

// ---------------------------------------------------------------------------
// Tensor-core flash attention, double-buffered K/V prefetch (R8 proven).
// Output: single fp16 (out-projection A is plain fp16 now).
// ---------------------------------------------------------------------------
#include <mma.h>
using namespace nvcuda;

#define QLD 136
#define SLD 132
#define PLD 72

#define OFF_QH 0
#define OFF_QL 17408
#define OFF_KV 34816          // per-buf: KH +0, V +17408
#define KVBUF  34816
#define OFF_S  104448
#define OFF_P  138240
#define OFF_O  147456
#define OFF_M  180224
#define OFF_L  180480
#define OFF_AL 180736
#define FLASH_SMEM 180992

__global__ void __launch_bounds__(256) flash_wmma(
    const __half* __restrict__ qh, const __half* __restrict__ ql,
    const __half* __restrict__ kh, const __half* __restrict__ vv,
    __half* __restrict__ attn)
{
    extern __shared__ char smc[];
    __half* sQh = (__half*)(smc + OFF_QH);
    __half* sQl = (__half*)(smc + OFF_QL);
    float*  sS  = (float*)(smc + OFF_S);
    __half* sP  = (__half*)(smc + OFF_P);
    float*  sO  = (float*)(smc + OFF_O);
    float*  sM  = (float*)(smc + OFF_M);
    float*  sL  = (float*)(smc + OFF_L);
    float*  sA  = (float*)(smc + OFF_AL);

    const int h     = blockIdx.x;
    const int ptile = (int)gridDim.y - 1 - blockIdx.y;
    const int m0    = ptile << 6;
    const int kvh   = h >> 3;
    const int tid   = threadIdx.x;
    const int wid   = tid >> 5;
    const int rs    = wid >> 1;
    const int ch    = wid & 1;
    const float scale = 0.08838834764831845f;

    auto load_kv = [&](int kb, int buf) {
        const int k0g = kb << 6;
        const uint32_t base = smem_u32(smc) + OFF_KV + buf * KVBUF;
#pragma unroll
        for (int i = 0; i < 4; i++) {
            int idx = tid + (i << 8);
            int r = idx >> 4, c = idx & 15;
            size_t so = (size_t)(k0g + r) * NKVD + kvh * HD + (c << 3);
            uint32_t off = r * (QLD * 2) + (c << 4);
            cpa16(base + off,         kh + so);
            cpa16(base + 17408 + off, vv + so);
        }
        CPA_COMMIT();
    };

    {
        uint32_t dqh = smem_u32(sQh), dql = smem_u32(sQl);
#pragma unroll
        for (int i = 0; i < 4; i++) {
            int idx = tid + (i << 8);
            int r = idx >> 4, c = idx & 15;
            size_t so = (size_t)(m0 + r) * NQ + h * HD + (c << 3);
            uint32_t off = r * (QLD * 2) + (c << 4);
            cpa16(dqh + off, qh + so);
            cpa16(dql + off, ql + so);
        }
        CPA_COMMIT();
    }
    load_kv(0, 0);

    for (int i = tid; i < 64 * 128 / 4; i += 256)
        ((float4*)sO)[i] = make_float4(0.f, 0.f, 0.f, 0.f);
    if (tid < 64) { sM[tid] = -1e30f; sL[tid] = 0.f; }

    for (int kb = 0; kb <= ptile; kb++) {
        const int k0g = kb << 6;
        const int buf = kb & 1;
        __half* sKh = (__half*)(smc + OFF_KV + buf * KVBUF);
        __half* sV  = (__half*)(smc + OFF_KV + buf * KVBUF + 17408);

        if (kb < ptile) { load_kv(kb + 1, buf ^ 1); CPA_WAIT1(); }
        else            { CPA_WAIT0(); }
        __syncthreads();

        // --- QK^T: (Qh + Ql) x Kh ---
        {
            wmma::fragment<wmma::accumulator, 16, 16, 16, float> accS[2];
            wmma::fill_fragment(accS[0], 0.0f);
            wmma::fill_fragment(accS[1], 0.0f);
#pragma unroll
            for (int k0 = 0; k0 < 128; k0 += 16) {
                wmma::fragment<wmma::matrix_a, 16, 16, 16, __half, wmma::row_major> ah, al;
                wmma::load_matrix_sync(ah, sQh + rs * 16 * QLD + k0, QLD);
                wmma::load_matrix_sync(al, sQl + rs * 16 * QLD + k0, QLD);
#pragma unroll
                for (int j = 0; j < 2; j++) {
                    wmma::fragment<wmma::matrix_b, 16, 16, 16, __half, wmma::col_major> bh;
                    int kcol = ch * 32 + j * 16;
                    wmma::load_matrix_sync(bh, sKh + kcol * QLD + k0, QLD);
                    wmma::mma_sync(accS[j], ah, bh, accS[j]);
                    wmma::mma_sync(accS[j], al, bh, accS[j]);
                }
            }
#pragma unroll
            for (int j = 0; j < 2; j++)
                wmma::store_matrix_sync(sS + rs * 16 * SLD + ch * 32 + j * 16,
                                        accS[j], SLD, wmma::mem_row_major);
        }
        __syncthreads();

        // --- online softmax ---
        {
            const int r  = tid >> 2;
            const int q4 = tid & 3;
            float* srow = sS + r * SLD + q4 * 16;
            const int qglob = m0 + r;
            const int kbase = k0g + q4 * 16;

            float vals[16];
            float mx = -1e30f;
#pragma unroll
            for (int j = 0; j < 16; j++) {
                float s = srow[j];
                s = (kbase + j <= qglob) ? s * scale : -1e30f;
                vals[j] = s;
                mx = fmaxf(mx, s);
            }
            mx = fmaxf(mx, __shfl_xor_sync(0xffffffffu, mx, 1));
            mx = fmaxf(mx, __shfl_xor_sync(0xffffffffu, mx, 2));

            float mold = sM[r];
            float mnew = fmaxf(mold, mx);
            float alpha = fexp(mold - mnew);

            __half* prow = sP + r * PLD + q4 * 16;
            float lsum = 0.f;
#pragma unroll
            for (int j = 0; j < 16; j++) {
                float p = fexp(vals[j] - mnew);
                prow[j] = __float2half(p);
                lsum += p;
            }
            lsum += __shfl_xor_sync(0xffffffffu, lsum, 1);
            lsum += __shfl_xor_sync(0xffffffffu, lsum, 2);

            if (q4 == 0) {
                sM[r] = mnew;
                sL[r] = sL[r] * alpha + lsum;
                sA[r] = alpha;
            }
        }
        __syncthreads();

        // --- P @ V ---
        {
            wmma::fragment<wmma::accumulator, 16, 16, 16, float> accO[4];
#pragma unroll
            for (int j = 0; j < 4; j++) wmma::fill_fragment(accO[j], 0.0f);
#pragma unroll
            for (int k0 = 0; k0 < 64; k0 += 16) {
                wmma::fragment<wmma::matrix_a, 16, 16, 16, __half, wmma::row_major> a;
                wmma::load_matrix_sync(a, sP + rs * 16 * PLD + k0, PLD);
#pragma unroll
                for (int j = 0; j < 4; j++) {
                    wmma::fragment<wmma::matrix_b, 16, 16, 16, __half, wmma::row_major> b;
                    wmma::load_matrix_sync(b, sV + k0 * QLD + ch * 64 + j * 16, QLD);
                    wmma::mma_sync(accO[j], a, b, accO[j]);
                }
            }
#pragma unroll
            for (int j = 0; j < 4; j++)
                wmma::store_matrix_sync(sS + rs * 16 * SLD + ch * 64 + j * 16,
                                        accO[j], SLD, wmma::mem_row_major);
        }
        __syncthreads();

        // --- O = O*alpha + PV ---
        {
            const int r  = tid >> 2;
            const int c0 = (tid & 3) << 5;
            const float a = sA[r];
            float4* op = (float4*)(sO + r * 128 + c0);
            const float4* pv = (const float4*)(sS + r * SLD + c0);
#pragma unroll
            for (int j = 0; j < 8; j++) {
                float4 o = op[j], p = pv[j];
                o.x = o.x * a + p.x;
                o.y = o.y * a + p.y;
                o.z = o.z * a + p.z;
                o.w = o.w * a + p.w;
                op[j] = o;
            }
        }
        __syncthreads();
    }

    // Epilogue: normalize, write fp16
    {
        const int r  = tid >> 2;
        const int c0 = (tid & 3) << 5;
        const float inv = 1.0f / sL[r];
        __half* base = attn + (size_t)(m0 + r) * NQ + h * HD + c0;
#pragma unroll
        for (int j = 0; j < 32; j++)
            base[j] = __float2half(sO[r * 128 + c0 + j] * inv);
    }
}

// ---------------------------------------------------------------------------
extern "C" void kernel_launch(void* const* d_in, const int* in_sizes, int n_in,
                              void* d_out, int out_size)
{
    (void)in_sizes; (void)n_in; (void)out_size;
    const float* x  = (const float*)d_in[0];
    const float* wq = (const float*)d_in[1];
    const float* wk = (const float*)d_in[2];
    const float* wv = (const float*)d_in[3];
    const float* wo = (const float*)d_in[4];
    const float* qn = (const float*)d_in[5];
    const float* kn = (const float*)d_in[6];
    const float* cs = (const float*)d_in[7];
    const float* sn = (const float*)d_in[8];
    float* out = (float*)d_out;

    float* qkv;
    cudaGetSymbolAddress((void**)&qkv, g_qkv);

    __half *x16, *wT, *woT, *at16;
    cudaGetSymbolAddress((void**)&x16,  g_x16);
    cudaGetSymbolAddress((void**)&wT,   g_wqkvT);
    cudaGetSymbolAddress((void**)&woT,  g_woT);
    cudaGetSymbolAddress((void**)&at16, g_at16);

    __half *q16h, *q16l, *k16h, *v16;
    cudaGetSymbolAddress((void**)&q16h, g_q16h);
    cudaGetSymbolAddress((void**)&q16l, g_q16l);
    cudaGetSymbolAddress((void**)&k16h, g_k16h);
    cudaGetSymbolAddress((void**)&v16,  g_v16);

    cudaFuncSetAttribute(gemm_mma_f16,
                         cudaFuncAttributeMaxDynamicSharedMemorySize, GEMM_SMEM);
    cudaFuncSetAttribute(flash_wmma,
                         cudaFuncAttributeMaxDynamicSharedMemorySize, FLASH_SMEM);

    // Convert activations to fp16; transpose weights to fp16 [N][K]
    cvt_f16v<<<(S_LEN * HID / 4 + 255) / 256, 256>>>(
        (const float4*)x, (uint2*)x16, S_LEN * HID / 4);
    transpose_f16<<<dim3(NQ / 32,   HID / 32), dim3(32, 8)>>>(wq, wT, HID, NQ);
    transpose_f16<<<dim3(NKVD / 32, HID / 32), dim3(32, 8)>>>(
        wk, wT + (size_t)NQ * HID, HID, NKVD);
    transpose_f16<<<dim3(NKVD / 32, HID / 32), dim3(32, 8)>>>(
        wv, wT + (size_t)(NQ + NKVD) * HID, HID, NKVD);
    transpose_f16<<<dim3(HID / 32,  NQ / 32),  dim3(32, 8)>>>(wo, woT, NQ, HID);

    // Fused QKV projection (single fp16 HMMA)
    gemm_mma_f16<<<dim3(NQKV / 128, S_LEN / 128), 256, GEMM_SMEM>>>(
        x16, wT, qkv, NQKV, HID);

    // RMSNorm + RoPE -> fp16 hi/lo (K: hi only); V -> fp16
    rmsnorm_rope_f16<<<S_LEN * NH,  128>>>(qkv, 0,  qn, cs, sn, NH,  q16h, q16l);
    rmsnorm_rope_f16<<<S_LEN * NKV, 128>>>(qkv, NQ, kn, cs, sn, NKV, k16h, (half*)0);
    cvt_v16<<<(S_LEN * NKVD) / 256, 256>>>(qkv, v16);

    // Flash attention -> fp16
    flash_wmma<<<dim3(NH, S_LEN / 64), 256, FLASH_SMEM>>>(
        q16h, q16l, k16h, v16, at16);

    // Output projection (single fp16 HMMA)
    gemm_mma_f16<<<dim3(HID / 128, S_LEN / 128), 256, GEMM_SMEM>>>(
        at16, woT, out, HID, NQ);
}